// round 2
// baseline (speedup 1.0000x reference)
#include <cuda_runtime.h>
#include <cuda_bf16.h>

#define TENC 48
#define TDEC 24
#define DSTEPS 30
#define HD 128
#define NF1 17
#define NF2 129
#define K1 145   // NF1 + HD
#define K2 257   // NF2 + HD
#define KD 256   // HD + HD
#define G 8
#define NSTAGECTA 128
#define NTH 256
#define NG 512
#define BTOT 1024

typedef unsigned long long u64;

// ---------------- device scratch (allocation-free) ----------------
__device__ float g_Wt1[K1 * NG];
__device__ float g_Wt2[K2 * NG];
__device__ float g_Wtd[KD * NG];
__device__ float g_Wet1[256 * TENC];
__device__ float g_Wet2[256 * TENC];
__device__ float g_Wdt[256 * HD];
__device__ float g_Udt[HD * HD];
__device__ float g_b1[NG], g_b2[NG], g_bd[NG];
__device__ float g_pre1[BTOT * NF1 * TENC];   // [b][f][s]
__device__ float g_pre2[BTOT * NF2 * TENC];   // [b][f][s]
__device__ float g_mid[BTOT * TENC * NF2];    // [b][t][f] (f=128 holds label)
__device__ float g_fin[BTOT * TENC * HD];     // [b][t][j]
__device__ float g_ud[BTOT * TENC * HD];      // [b][t][j]

// ---------------- math helpers ----------------
__device__ __forceinline__ float tanha(float x) {
    float y; asm("tanh.approx.f32 %0, %1;" : "=f"(y) : "f"(x)); return y;
}
__device__ __forceinline__ float sigf(float x) {
    return __fdividef(1.f, 1.f + __expf(-x));
}
__device__ __forceinline__ float tanhacc(float x) {
    x = fminf(fmaxf(x, -15.f), 15.f);
    float e = __expf(2.f * x);
    return __fdividef(e - 1.f, e + 1.f);
}
__device__ __forceinline__ u64 fma2(u64 a, u64 b, u64 c) {
    u64 d; asm("fma.rn.f32x2 %0, %1, %2, %3;" : "=l"(d) : "l"(a), "l"(b), "l"(c)); return d;
}
__device__ __forceinline__ u64 dup2(float x) {
    u64 d; unsigned r = __float_as_uint(x);
    asm("mov.b64 %0, {%1, %1};" : "=l"(d) : "r"(r)); return d;
}
__device__ __forceinline__ float2 unpack2(u64 a) {
    unsigned l, h;
    asm("mov.b64 {%0, %1}, %2;" : "=r"(l), "=r"(h) : "l"(a));
    return make_float2(__uint_as_float(l), __uint_as_float(h));
}

struct __align__(16) Smem {
    float hc[G][256];        // [h(128) | c(128)]
    float we[G][HD];         // we / wd
    float score[G][132];
    float alpha[G][132];
    float inpair[260][G];    // packed gate inputs, pair-of-g for f32x2
    float gates[G][NG];
    float vvec[136];         // Ve/Vd (+ bias at [130])
    float vreg[132];         // reg_W (+ reg_b at [130]) - decoder only
};

// warp-cooperative softmax over F entries of score_row -> alpha_row
__device__ __forceinline__ void warp_softmax(const float* score_row, float* alpha_row,
                                             int F, int lane) {
    float mx = -1e30f;
    for (int f = lane; f < F; f += 32) mx = fmaxf(mx, score_row[f]);
#pragma unroll
    for (int o = 16; o; o >>= 1) mx = fmaxf(mx, __shfl_xor_sync(0xffffffffu, mx, o));
    float sm = 0.f;
    for (int f = lane; f < F; f += 32) {
        float e = __expf(score_row[f] - mx);
        alpha_row[f] = e;
        sm += e;
    }
#pragma unroll
    for (int o = 16; o; o >>= 1) sm += __shfl_xor_sync(0xffffffffu, sm, o);
    float inv = __fdividef(1.f, sm);
    for (int f = lane; f < F; f += 32) alpha_row[f] *= inv;
}

// gate GEMM: gates[g][n] = sum_k inpair[k][g] * Wt[k][n] + bsum[n]
template <int K>
__device__ __forceinline__ void gates_gemm(const float* __restrict__ Wt,
                                           const float* __restrict__ bsum,
                                           Smem& s, int tid) {
    const int n0 = 2 * tid;
    u64 aA[4], aB[4];
#pragma unroll
    for (int p = 0; p < 4; p++) { aA[p] = 0ull; aB[p] = 0ull; }
#pragma unroll 4
    for (int k = 0; k < K; k++) {
        float2 w = *(const float2*)(Wt + (size_t)k * NG + n0);
        u64 w0 = dup2(w.x), w1 = dup2(w.y);
        const u64* ip = (const u64*)&s.inpair[k][0];
#pragma unroll
        for (int p = 0; p < 4; p++) {
            u64 x2 = ip[p];
            aA[p] = fma2(w0, x2, aA[p]);
            aB[p] = fma2(w1, x2, aB[p]);
        }
    }
    float b0 = bsum[n0], b1 = bsum[n0 + 1];
#pragma unroll
    for (int p = 0; p < 4; p++) {
        float2 va = unpack2(aA[p]);
        float2 vb = unpack2(aB[p]);
        s.gates[2 * p][n0]         = va.x + b0;
        s.gates[2 * p + 1][n0]     = va.y + b0;
        s.gates[2 * p][n0 + 1]     = vb.x + b1;
        s.gates[2 * p + 1][n0 + 1] = vb.y + b1;
    }
}

// LSTM cell update from s.gates into s.hc; optionally store h to out[j]
__device__ __forceinline__ void cell_update(Smem& s, int tid, int bid,
                                            float* __restrict__ outbase, int ostride) {
    for (int idx = tid; idx < G * HD; idx += NTH) {
        int g = idx >> 7, j = idx & 127;
        float gi = s.gates[g][j];
        float gf = s.gates[g][HD + j];
        float gg = s.gates[g][2 * HD + j];
        float go = s.gates[g][3 * HD + j];
        float c  = s.hc[g][HD + j];
        float c2 = sigf(gf) * c + sigf(gi) * tanhacc(gg);
        float h  = sigf(go) * tanhacc(c2);
        s.hc[g][j] = h;
        s.hc[g][HD + j] = c2;
        if (outbase) {
            int b = bid * G + g;
            outbase[(size_t)b * ostride + j] = h;
        }
    }
}

// ---------------- setup: transpose/concat weights ----------------
__global__ void setup_kernel(
    const float* __restrict__ e1_Wih, const float* __restrict__ e1_Whh,
    const float* __restrict__ e2_Wih, const float* __restrict__ e2_Whh,
    const float* __restrict__ d_Wih,  const float* __restrict__ d_Whh,
    const float* __restrict__ We1,    const float* __restrict__ We2,
    const float* __restrict__ Wd,     const float* __restrict__ Ud,
    const float* __restrict__ e1_bih, const float* __restrict__ e1_bhh,
    const float* __restrict__ e2_bih, const float* __restrict__ e2_bhh,
    const float* __restrict__ d_bih,  const float* __restrict__ d_bhh) {
    int tid = blockIdx.x * blockDim.x + threadIdx.x;
    int nt = gridDim.x * blockDim.x;
    for (int i = tid; i < K1 * NG; i += nt) {
        int k = i / NG, n = i % NG;
        g_Wt1[i] = (k < NF1) ? e1_Wih[n * NF1 + k] : e1_Whh[n * HD + (k - NF1)];
    }
    for (int i = tid; i < K2 * NG; i += nt) {
        int k = i / NG, n = i % NG;
        g_Wt2[i] = (k < NF2) ? e2_Wih[n * NF2 + k] : e2_Whh[n * HD + (k - NF2)];
    }
    for (int i = tid; i < KD * NG; i += nt) {
        int k = i / NG, n = i % NG;
        g_Wtd[i] = (k < HD) ? d_Wih[n * HD + k] : d_Whh[n * HD + (k - HD)];
    }
    for (int i = tid; i < 256 * TENC; i += nt) {
        int k = i / TENC, ss = i % TENC;
        g_Wet1[i] = We1[ss * 256 + k];
        g_Wet2[i] = We2[ss * 256 + k];
    }
    for (int i = tid; i < 256 * HD; i += nt) {
        int k = i / HD, j = i % HD;
        g_Wdt[i] = Wd[j * 256 + k];
    }
    for (int i = tid; i < HD * HD; i += nt) {
        int k = i / HD, j = i % HD;
        g_Udt[i] = Ud[j * HD + k];
    }
    for (int i = tid; i < NG; i += nt) {
        g_b1[i] = e1_bih[i] + e1_bhh[i];
        g_b2[i] = e2_bih[i] + e2_bhh[i];
        g_bd[i] = d_bih[i] + d_bhh[i];
    }
}

// ---------------- pre1: pre1[b][f][s] = sum_t x[b][t][f]*Ue1[s][t] + Ue1_b[s]
// also deposits labels into g_mid[b][t][128]
__global__ __launch_bounds__(NTH) void pre1_kernel(
    const float* __restrict__ inp, const float* __restrict__ lab,
    const float* __restrict__ Ue1, const float* __restrict__ Ue1b) {
    __shared__ float xs[TENC * NF1];
    __shared__ float ue[TENC * TENC];
    int b = blockIdx.x, tid = threadIdx.x;
    for (int i = tid; i < TENC * NF1; i += NTH) {
        int t = i / NF1, f = i % NF1;
        xs[i] = inp[((size_t)b * TENC + t) * 18 + f + 1];
    }
    for (int i = tid; i < TENC * TENC; i += NTH) ue[i] = Ue1[i];  // ue[s][t]
    for (int i = tid; i < TENC; i += NTH)
        g_mid[((size_t)b * TENC + i) * NF2 + HD] = lab[(size_t)b * TENC + i];
    __syncthreads();
    for (int i = tid; i < NF1 * TENC; i += NTH) {
        int f = i / TENC, ss = i % TENC;
        float a = 0.f;
#pragma unroll 8
        for (int t = 0; t < TENC; t++) a += xs[t * NF1 + f] * ue[ss * TENC + t];
        g_pre1[((size_t)b * NF1 + f) * TENC + ss] = a + Ue1b[ss];
    }
}

// ---------------- pre2: pre2[b][f][s] = sum_t mid[b][t][f]*Ue2[s][t] + Ue2_b[s]
__global__ __launch_bounds__(NTH) void pre2_kernel(
    const float* __restrict__ Ue2, const float* __restrict__ Ue2b) {
    __shared__ float ms[TENC * NF2];
    __shared__ float ue[TENC * TENC];
    int b = blockIdx.x, tid = threadIdx.x;
    for (int i = tid; i < TENC * NF2; i += NTH) ms[i] = g_mid[(size_t)b * TENC * NF2 + i];
    for (int i = tid; i < TENC * TENC; i += NTH) ue[i] = Ue2[i];
    __syncthreads();
    for (int i = tid; i < NF2 * TENC; i += NTH) {
        int f = i / TENC, ss = i % TENC;
        float a = 0.f;
#pragma unroll 8
        for (int t = 0; t < TENC; t++) a += ms[t * NF2 + f] * ue[ss * TENC + t];
        g_pre2[((size_t)b * NF2 + f) * TENC + ss] = a + Ue2b[ss];
    }
}

// ---------------- ud: ud[b][t][j] = sum_k fin[b][t][k]*Ud[j][k] + Ud_b[j]
__global__ __launch_bounds__(NTH) void ud_kernel(const float* __restrict__ Udb) {
    __shared__ float fs[TENC * HD];
    int b = blockIdx.x, tid = threadIdx.x;
    for (int i = tid; i < TENC * HD; i += NTH) fs[i] = g_fin[(size_t)b * TENC * HD + i];
    __syncthreads();
    for (int i = tid; i < TENC * HD; i += NTH) {
        int t = i / HD, j = i % HD;
        float a = 0.f;
#pragma unroll 8
        for (int k = 0; k < HD; k++) a += fs[t * HD + k] * g_Udt[k * HD + j];
        g_ud[(size_t)b * TENC * HD + i] = a + Udb[j];
    }
}

// ---------------- stage 1 & 2 (encoder scans) ----------------
template <int K, int NF>
__global__ __launch_bounds__(NTH) void stage_kernel(
    const float* __restrict__ inp,      // stage1: input_p_q; stage2: unused
    const float* __restrict__ Ve, const float* __restrict__ Veb,
    const float* __restrict__ Wt, const float* __restrict__ bsum,
    const float* __restrict__ Wet, const float* __restrict__ pre,
    float* __restrict__ outb, int ostride) {
    __shared__ Smem s;
    int tid = threadIdx.x, bid = blockIdx.x;
    int wid = tid >> 5, lane = tid & 31;

    for (int i = tid; i < G * 256; i += NTH) ((float*)s.hc)[i] = 0.f;
    for (int i = tid; i < TENC; i += NTH) s.vvec[i] = Ve[i];
    if (tid == 0) s.vvec[130] = Veb[0];

    for (int t = 0; t < TENC; t++) {
        __syncthreads();
        // we[g][ss] = hc . Wet[:,ss]
        for (int idx = tid; idx < G * TENC; idx += NTH) {
            int g = idx / TENC, ss = idx % TENC;
            float a = 0.f;
#pragma unroll 8
            for (int k = 0; k < 256; k++) a += s.hc[g][k] * Wet[k * TENC + ss];
            s.we[g][ss] = a;
        }
        __syncthreads();
        // score[g][f] = sum_s tanh(we+pre)*Ve + Veb
        for (int idx = tid; idx < G * NF; idx += NTH) {
            int g = idx / NF, f = idx % NF;
            int b = bid * G + g;
            const float* pr = pre + ((size_t)b * NF + f) * TENC;
            float a = 0.f;
#pragma unroll 8
            for (int ss = 0; ss < TENC; ss++)
                a += tanha(s.we[g][ss] + pr[ss]) * s.vvec[ss];
            s.score[g][f] = a + s.vvec[130];
        }
        __syncthreads();
        if (wid < G) warp_softmax(s.score[wid], s.alpha[wid], NF, lane);
        __syncthreads();
        // build gate input: [x_t*alpha | h]
        for (int idx = tid; idx < K * G; idx += NTH) {
            int k = idx >> 3, g = idx & 7;
            int b = bid * G + g;
            float v;
            if (k < NF) {
                float xv;
                if (NF == NF1)
                    xv = inp[((size_t)b * TENC + t) * 18 + k + 1];
                else
                    xv = g_mid[((size_t)b * TENC + t) * NF2 + k];
                v = xv * s.alpha[g][k];
            } else {
                v = s.hc[g][k - NF];
            }
            s.inpair[k][g] = v;
        }
        __syncthreads();
        gates_gemm<K>(Wt, bsum, s, tid);
        __syncthreads();
        float* ob = outb + (size_t)t * ostride * 0;  // dummy to keep signature simple
        (void)ob;
        // write h to out[b][t][:]
        for (int idx = tid; idx < G * HD; idx += NTH) {
            int g = idx >> 7, j = idx & 127;
            float gi = s.gates[g][j];
            float gf = s.gates[g][HD + j];
            float gg = s.gates[g][2 * HD + j];
            float go = s.gates[g][3 * HD + j];
            float c  = s.hc[g][HD + j];
            float c2 = sigf(gf) * c + sigf(gi) * tanhacc(gg);
            float h  = sigf(go) * tanhacc(c2);
            s.hc[g][j] = h;
            s.hc[g][HD + j] = c2;
            int b = bid * G + g;
            outb[((size_t)b * TENC + t) * ostride + j] = h;
        }
    }
}

// ---------------- decoder ----------------
__global__ __launch_bounds__(NTH) void decoder_kernel(
    const float* __restrict__ Vd, const float* __restrict__ Vdb,
    const float* __restrict__ regW, const float* __restrict__ regb,
    float* __restrict__ out) {
    __shared__ Smem s;
    int tid = threadIdx.x, bid = blockIdx.x;
    int wid = tid >> 5, lane = tid & 31;

    for (int i = tid; i < G * 256; i += NTH) ((float*)s.hc)[i] = 0.f;
    for (int i = tid; i < HD; i += NTH) { s.vvec[i] = Vd[i]; s.vreg[i] = regW[i]; }
    if (tid == 0) { s.vvec[130] = Vdb[0]; s.vreg[130] = regb[0]; }

    for (int sd = 0; sd < DSTEPS; sd++) {
        __syncthreads();
        // wd[g][j] = hc . Wdt[:,j]
        for (int idx = tid; idx < G * HD; idx += NTH) {
            int g = idx >> 7, j = idx & 127;
            float a = 0.f;
#pragma unroll 8
            for (int k = 0; k < 256; k++) a += s.hc[g][k] * g_Wdt[k * HD + j];
            s.we[g][j] = a;
        }
        __syncthreads();
        // score[g][t] = sum_j tanh(wd[j]+ud[t][j])*Vd[j] + Vdb
        for (int idx = tid; idx < G * TENC; idx += NTH) {
            int g = idx / TENC, tt = idx % TENC;
            int b = bid * G + g;
            const float* udp = g_ud + ((size_t)b * TENC + tt) * HD;
            float a = 0.f;
#pragma unroll 8
            for (int j = 0; j < HD; j++)
                a += tanha(s.we[g][j] + udp[j]) * s.vvec[j];
            s.score[g][tt] = a + s.vvec[130];
        }
        __syncthreads();
        if (wid < G) warp_softmax(s.score[wid], s.alpha[wid], TENC, lane);
        __syncthreads();
        // din[g][j] = sum_t alpha[t]*fin[b][t][j];  inpair = [din | h]
        for (int idx = tid; idx < HD * G; idx += NTH) {
            int j = idx >> 3, g = idx & 7;
            int b = bid * G + g;
            const float* fp = g_fin + (size_t)b * TENC * HD + j;
            float a = 0.f;
#pragma unroll 8
            for (int tt = 0; tt < TENC; tt++) a += s.alpha[g][tt] * fp[tt * HD];
            s.inpair[j][g] = a;
            s.inpair[HD + j][g] = s.hc[g][j];
        }
        __syncthreads();
        gates_gemm<KD>(g_Wtd, g_bd, s, tid);
        __syncthreads();
        cell_update(s, tid, bid, nullptr, 0);
        __syncthreads();
        // output regression for last TDEC steps
        if (sd >= DSTEPS - TDEC && wid < G) {
            float a = 0.f;
#pragma unroll
            for (int r = 0; r < 4; r++) a += s.hc[wid][lane + 32 * r] * s.vreg[lane + 32 * r];
#pragma unroll
            for (int o = 16; o; o >>= 1) a += __shfl_xor_sync(0xffffffffu, a, o);
            if (lane == 0) {
                int b = bid * G + wid;
                out[(size_t)b * TDEC + (sd - (DSTEPS - TDEC))] = a + s.vreg[130];
            }
        }
    }
}

// ---------------- launch ----------------
extern "C" void kernel_launch(void* const* d_in, const int* in_sizes, int n_in,
                              void* d_out, int out_size) {
    const float* input_p_q = (const float*)d_in[0];
    const float* label_p   = (const float*)d_in[1];
    const float* Ue1_W = (const float*)d_in[2];
    const float* Ue1_b = (const float*)d_in[3];
    const float* We1_W = (const float*)d_in[4];
    const float* Ve1_W = (const float*)d_in[5];
    const float* Ve1_b = (const float*)d_in[6];
    const float* Ue2_W = (const float*)d_in[7];
    const float* Ue2_b = (const float*)d_in[8];
    const float* We2_W = (const float*)d_in[9];
    const float* Ve2_W = (const float*)d_in[10];
    const float* Ve2_b = (const float*)d_in[11];
    const float* Ud_W  = (const float*)d_in[12];
    const float* Ud_b  = (const float*)d_in[13];
    const float* Wd_W  = (const float*)d_in[14];
    const float* Vd_W  = (const float*)d_in[15];
    const float* Vd_b  = (const float*)d_in[16];
    const float* e1_Wih = (const float*)d_in[17];
    const float* e1_Whh = (const float*)d_in[18];
    const float* e1_bih = (const float*)d_in[19];
    const float* e1_bhh = (const float*)d_in[20];
    const float* e2_Wih = (const float*)d_in[21];
    const float* e2_Whh = (const float*)d_in[22];
    const float* e2_bih = (const float*)d_in[23];
    const float* e2_bhh = (const float*)d_in[24];
    const float* d_Wih  = (const float*)d_in[25];
    const float* d_Whh  = (const float*)d_in[26];
    const float* d_bih  = (const float*)d_in[27];
    const float* d_bhh  = (const float*)d_in[28];
    const float* reg_W  = (const float*)d_in[29];
    const float* reg_b  = (const float*)d_in[30];
    float* out = (float*)d_out;

    float *p_Wt1, *p_Wt2, *p_Wtd, *p_Wet1, *p_Wet2;
    float *p_b1, *p_b2, *p_pre1, *p_pre2, *p_mid, *p_fin;
    cudaGetSymbolAddress((void**)&p_Wt1, g_Wt1);
    cudaGetSymbolAddress((void**)&p_Wt2, g_Wt2);
    cudaGetSymbolAddress((void**)&p_Wtd, g_Wtd);
    cudaGetSymbolAddress((void**)&p_Wet1, g_Wet1);
    cudaGetSymbolAddress((void**)&p_Wet2, g_Wet2);
    cudaGetSymbolAddress((void**)&p_b1, g_b1);
    cudaGetSymbolAddress((void**)&p_b2, g_b2);
    cudaGetSymbolAddress((void**)&p_pre1, g_pre1);
    cudaGetSymbolAddress((void**)&p_pre2, g_pre2);
    cudaGetSymbolAddress((void**)&p_mid, g_mid);
    cudaGetSymbolAddress((void**)&p_fin, g_fin);

    setup_kernel<<<128, 256>>>(e1_Wih, e1_Whh, e2_Wih, e2_Whh, d_Wih, d_Whh,
                               We1_W, We2_W, Wd_W, Ud_W,
                               e1_bih, e1_bhh, e2_bih, e2_bhh, d_bih, d_bhh);
    pre1_kernel<<<BTOT, NTH>>>(input_p_q, label_p, Ue1_W, Ue1_b);
    stage_kernel<K1, NF1><<<NSTAGECTA, NTH>>>(input_p_q, Ve1_W, Ve1_b,
                                              p_Wt1, p_b1, p_Wet1, p_pre1,
                                              p_mid, NF2);
    pre2_kernel<<<BTOT, NTH>>>(Ue2_W, Ue2_b);
    stage_kernel<K2, NF2><<<NSTAGECTA, NTH>>>(input_p_q, Ve2_W, Ve2_b,
                                              p_Wt2, p_b2, p_Wet2, p_pre2,
                                              p_fin, HD);
    ud_kernel<<<BTOT, NTH>>>(Ud_b);
    decoder_kernel<<<NSTAGECTA, NTH>>>(Vd_W, Vd_b, reg_W, reg_b, out);
}

// round 3
// speedup vs baseline: 2.0240x; 2.0240x over previous
#include <cuda_runtime.h>
#include <cuda_bf16.h>

#define TENC 48
#define TDEC 24
#define DSTEPS 30
#define HD 128
#define NF1 17
#define NF2 129
#define K1 145   // NF1 + HD
#define K2 257   // NF2 + HD
#define KD 256   // HD + HD
#define G 8
#define NCTA 128
#define NTH 512
#define NG 512
#define BTOT 1024
#define HCT_STR 10

typedef unsigned long long u64;

// ---------------- device scratch (allocation-free) ----------------
__device__ float g_Wt1[K1 * NG];
__device__ float g_Wt2[K2 * NG];
__device__ float g_Wtd[KD * NG];
__device__ float g_Wet1[256 * TENC];
__device__ float g_Wet2[256 * TENC];
__device__ float g_Wdt[256 * HD];
__device__ float g_Udt[HD * HD];
__device__ float g_b1[NG], g_b2[NG], g_bd[NG];
__device__ float g_pre1[BTOT * TENC * NF1];   // [b][s][f]
__device__ float g_pre2[BTOT * TENC * NF2];   // [b][s][f]
__device__ float g_mid[BTOT * TENC * NF2];    // [b][t][f] (f=128 holds label)
__device__ float g_fin[BTOT * TENC * HD];     // [b][t][j]
__device__ float g_udT[BTOT * HD * TENC];     // [b][j][t]

// ---------------- math helpers ----------------
__device__ __forceinline__ float tanha(float x) {
    float y; asm("tanh.approx.f32 %0, %1;" : "=f"(y) : "f"(x)); return y;
}
__device__ __forceinline__ float sigf(float x) {
    return __fdividef(1.f, 1.f + __expf(-x));
}
__device__ __forceinline__ float tanhacc(float x) {
    x = fminf(fmaxf(x, -15.f), 15.f);
    float e = __expf(2.f * x);
    return __fdividef(e - 1.f, e + 1.f);
}
__device__ __forceinline__ u64 fma2(u64 a, u64 b, u64 c) {
    u64 d; asm("fma.rn.f32x2 %0, %1, %2, %3;" : "=l"(d) : "l"(a), "l"(b), "l"(c)); return d;
}
__device__ __forceinline__ u64 dup2(float x) {
    u64 d; unsigned r = __float_as_uint(x);
    asm("mov.b64 %0, {%1, %1};" : "=l"(d) : "r"(r)); return d;
}
__device__ __forceinline__ float2 unpack2(u64 a) {
    unsigned l, h;
    asm("mov.b64 {%0, %1}, %2;" : "=r"(l), "=r"(h) : "l"(a));
    return make_float2(__uint_as_float(l), __uint_as_float(h));
}

// warp-cooperative softmax over F entries
__device__ __forceinline__ void warp_softmax(const float* score_row, float* alpha_row,
                                             int F, int lane) {
    float mx = -1e30f;
    for (int f = lane; f < F; f += 32) mx = fmaxf(mx, score_row[f]);
#pragma unroll
    for (int o = 16; o; o >>= 1) mx = fmaxf(mx, __shfl_xor_sync(0xffffffffu, mx, o));
    float sm = 0.f;
    for (int f = lane; f < F; f += 32) {
        float e = __expf(score_row[f] - mx);
        alpha_row[f] = e;
        sm += e;
    }
#pragma unroll
    for (int o = 16; o; o >>= 1) sm += __shfl_xor_sync(0xffffffffu, sm, o);
    float inv = __fdividef(1.f, sm);
    for (int f = lane; f < F; f += 32) alpha_row[f] *= inv;
}

// gate GEMM: gates[g][n] = sum_k inpair[k][g]*Wt[k][n] + bsum[n]; threads 0..255, 2 cols each
template <int K>
__device__ __forceinline__ void gates_gemm(const float* __restrict__ Wt,
                                           const float* __restrict__ bsum,
                                           const float* __restrict__ inpair,
                                           float* __restrict__ gates, int tid) {
    if (tid >= 256) return;
    const int n0 = 2 * tid;
    u64 a0 = 0, a1 = 0, a2 = 0, a3 = 0, a4 = 0, a5 = 0, a6 = 0, a7 = 0;
#pragma unroll 4
    for (int k = 0; k < K; k++) {
        float2 w = *(const float2*)(Wt + (size_t)k * NG + n0);
        u64 w0 = dup2(w.x), w1 = dup2(w.y);
        const u64* ip = (const u64*)(inpair + k * G);
        u64 i0 = ip[0], i1 = ip[1], i2 = ip[2], i3 = ip[3];
        a0 = fma2(w0, i0, a0); a1 = fma2(w0, i1, a1);
        a2 = fma2(w0, i2, a2); a3 = fma2(w0, i3, a3);
        a4 = fma2(w1, i0, a4); a5 = fma2(w1, i1, a5);
        a6 = fma2(w1, i2, a6); a7 = fma2(w1, i3, a7);
    }
    float b0 = bsum[n0], b1 = bsum[n0 + 1];
    float2 r;
    r = unpack2(a0); gates[0 * NG + n0] = r.x + b0; gates[1 * NG + n0] = r.y + b0;
    r = unpack2(a1); gates[2 * NG + n0] = r.x + b0; gates[3 * NG + n0] = r.y + b0;
    r = unpack2(a2); gates[4 * NG + n0] = r.x + b0; gates[5 * NG + n0] = r.y + b0;
    r = unpack2(a3); gates[6 * NG + n0] = r.x + b0; gates[7 * NG + n0] = r.y + b0;
    r = unpack2(a4); gates[0 * NG + n0 + 1] = r.x + b1; gates[1 * NG + n0 + 1] = r.y + b1;
    r = unpack2(a5); gates[2 * NG + n0 + 1] = r.x + b1; gates[3 * NG + n0 + 1] = r.y + b1;
    r = unpack2(a6); gates[4 * NG + n0 + 1] = r.x + b1; gates[5 * NG + n0 + 1] = r.y + b1;
    r = unpack2(a7); gates[6 * NG + n0 + 1] = r.x + b1; gates[7 * NG + n0 + 1] = r.y + b1;
}

// ---------------- setup: transpose/concat weights ----------------
__global__ void setup_kernel(
    const float* __restrict__ e1_Wih, const float* __restrict__ e1_Whh,
    const float* __restrict__ e2_Wih, const float* __restrict__ e2_Whh,
    const float* __restrict__ d_Wih,  const float* __restrict__ d_Whh,
    const float* __restrict__ We1,    const float* __restrict__ We2,
    const float* __restrict__ Wd,     const float* __restrict__ Ud,
    const float* __restrict__ e1_bih, const float* __restrict__ e1_bhh,
    const float* __restrict__ e2_bih, const float* __restrict__ e2_bhh,
    const float* __restrict__ d_bih,  const float* __restrict__ d_bhh) {
    int tid = blockIdx.x * blockDim.x + threadIdx.x;
    int nt = gridDim.x * blockDim.x;
    for (int i = tid; i < K1 * NG; i += nt) {
        int k = i / NG, n = i % NG;
        g_Wt1[i] = (k < NF1) ? e1_Wih[n * NF1 + k] : e1_Whh[n * HD + (k - NF1)];
    }
    for (int i = tid; i < K2 * NG; i += nt) {
        int k = i / NG, n = i % NG;
        g_Wt2[i] = (k < NF2) ? e2_Wih[n * NF2 + k] : e2_Whh[n * HD + (k - NF2)];
    }
    for (int i = tid; i < KD * NG; i += nt) {
        int k = i / NG, n = i % NG;
        g_Wtd[i] = (k < HD) ? d_Wih[n * HD + k] : d_Whh[n * HD + (k - HD)];
    }
    for (int i = tid; i < 256 * TENC; i += nt) {
        int k = i / TENC, ss = i % TENC;
        g_Wet1[i] = We1[ss * 256 + k];
        g_Wet2[i] = We2[ss * 256 + k];
    }
    for (int i = tid; i < 256 * HD; i += nt) {
        int k = i / HD, j = i % HD;
        g_Wdt[i] = Wd[j * 256 + k];
    }
    for (int i = tid; i < HD * HD; i += nt) {
        int k = i / HD, j = i % HD;
        g_Udt[i] = Ud[j * HD + k];
    }
    for (int i = tid; i < NG; i += nt) {
        g_b1[i] = e1_bih[i] + e1_bhh[i];
        g_b2[i] = e2_bih[i] + e2_bhh[i];
        g_bd[i] = d_bih[i] + d_bhh[i];
    }
}

// ---------------- pre1: pre1[b][s][f] = sum_t x[b][t][f]*Ue1[s][t] + Ue1_b[s]
__global__ __launch_bounds__(256) void pre1_kernel(
    const float* __restrict__ inp, const float* __restrict__ lab,
    const float* __restrict__ Ue1, const float* __restrict__ Ue1b) {
    __shared__ float xs[TENC * NF1];
    __shared__ float ue[TENC * TENC];
    int b = blockIdx.x, tid = threadIdx.x;
    for (int i = tid; i < TENC * NF1; i += 256) {
        int t = i / NF1, f = i % NF1;
        xs[i] = inp[((size_t)b * TENC + t) * 18 + f + 1];
    }
    for (int i = tid; i < TENC * TENC; i += 256) ue[i] = Ue1[i];
    for (int i = tid; i < TENC; i += 256)
        g_mid[((size_t)b * TENC + i) * NF2 + HD] = lab[(size_t)b * TENC + i];
    __syncthreads();
    for (int i = tid; i < TENC * NF1; i += 256) {
        int ss = i / NF1, f = i % NF1;
        float a = 0.f;
#pragma unroll 8
        for (int t = 0; t < TENC; t++) a += xs[t * NF1 + f] * ue[ss * TENC + t];
        g_pre1[(size_t)b * TENC * NF1 + i] = a + Ue1b[ss];
    }
}

// ---------------- pre2: pre2[b][s][f] = sum_t mid[b][t][f]*Ue2[s][t] + Ue2_b[s]
__global__ __launch_bounds__(256) void pre2_kernel(
    const float* __restrict__ Ue2, const float* __restrict__ Ue2b) {
    __shared__ float ms[TENC * NF2];
    __shared__ float ue[TENC * TENC];
    int b = blockIdx.x, tid = threadIdx.x;
    for (int i = tid; i < TENC * NF2; i += 256) ms[i] = g_mid[(size_t)b * TENC * NF2 + i];
    for (int i = tid; i < TENC * TENC; i += 256) ue[i] = Ue2[i];
    __syncthreads();
    for (int i = tid; i < TENC * NF2; i += 256) {
        int ss = i / NF2, f = i % NF2;
        float a = 0.f;
#pragma unroll 8
        for (int t = 0; t < TENC; t++) a += ms[t * NF2 + f] * ue[ss * TENC + t];
        g_pre2[(size_t)b * TENC * NF2 + i] = a + Ue2b[ss];
    }
}

// ---------------- ud: udT[b][j][t] = sum_k fin[b][t][k]*Ud[j][k] + Ud_b[j]
__global__ __launch_bounds__(256) void ud_kernel(const float* __restrict__ Udb) {
    extern __shared__ float sm_ud[];
    float* udt = sm_ud;             // 16384
    float* fs  = sm_ud + 16384;     // 48*129 padded
    int b = blockIdx.x, tid = threadIdx.x;
    for (int i = tid; i < HD * HD; i += 256) udt[i] = g_Udt[i];
    for (int i = tid; i < TENC * HD; i += 256) {
        int t = i >> 7, k = i & 127;
        fs[t * 129 + k] = g_fin[(size_t)b * TENC * HD + i];
    }
    __syncthreads();
    for (int u = tid; u < 32 * TENC; u += 256) {
        int t = u % TENC, jq = u / TENC;
        int j0 = 4 * jq;
        float a0 = Udb[j0], a1 = Udb[j0 + 1], a2 = Udb[j0 + 2], a3 = Udb[j0 + 3];
#pragma unroll 8
        for (int k = 0; k < HD; k++) {
            float f = fs[t * 129 + k];
            float4 uu = *(const float4*)(udt + k * HD + j0);
            a0 += f * uu.x; a1 += f * uu.y; a2 += f * uu.z; a3 += f * uu.w;
        }
        size_t base = (size_t)b * HD * TENC;
        g_udT[base + (size_t)(j0 + 0) * TENC + t] = a0;
        g_udT[base + (size_t)(j0 + 1) * TENC + t] = a1;
        g_udT[base + (size_t)(j0 + 2) * TENC + t] = a2;
        g_udT[base + (size_t)(j0 + 3) * TENC + t] = a3;
    }
}

// ---------------- stage smem layout (floats) ----------------
#define S_WET    0
#define S_HC     12288
#define S_HCT    14336
#define S_WE     16896
#define S_SCORE  17280
#define S_ALPHA  18336
#define S_INPAIR 19392
#define S_GATES  21472
#define S_VVEC   25568
#define STAGE_SMEM_FLOATS 25704

// ---------------- stage 1 & 2 (encoder scans) ----------------
template <int K, int NF>
__global__ __launch_bounds__(NTH, 1) void stage_kernel(
    const float* __restrict__ inp,
    const float* __restrict__ Ve, const float* __restrict__ Veb,
    const float* __restrict__ Wt, const float* __restrict__ bsum,
    const float* __restrict__ Wet, const float* __restrict__ pre,
    float* __restrict__ outb, int ostride) {
    extern __shared__ float sm[];
    float* wet    = sm + S_WET;
    float* hc     = sm + S_HC;
    float* hcT    = sm + S_HCT;
    float* we     = sm + S_WE;
    float* score  = sm + S_SCORE;
    float* alpha  = sm + S_ALPHA;
    float* inpair = sm + S_INPAIR;
    float* gates  = sm + S_GATES;
    float* vvec   = sm + S_VVEC;

    const int tid = threadIdx.x, bid = blockIdx.x;
    const int wid = tid >> 5, lane = tid & 31;

    for (int i = tid; i < 256 * TENC; i += NTH) wet[i] = Wet[i];
    for (int i = tid; i < G * 256; i += NTH) hc[i] = 0.f;
    for (int i = tid; i < 256 * HCT_STR; i += NTH) hcT[i] = 0.f;
    for (int i = tid; i < TENC; i += NTH) vvec[i] = Ve[i];
    if (tid == 0) vvec[130] = Veb[0];
    __syncthreads();

    const int NITEM = G * NF;
    // precompute score-item mapping
    int i0 = tid, i1 = tid + NTH, i2 = tid + 2 * NTH;
    bool v0 = i0 < NITEM, v1 = i1 < NITEM, v2 = i2 < NITEM;
    int g0 = v0 ? i0 / NF : 0, f0 = v0 ? i0 % NF : 0;
    int g1 = v1 ? i1 / NF : 0, f1 = v1 ? i1 % NF : 0;
    int g2 = v2 ? i2 / NF : 0, f2 = v2 ? i2 % NF : 0;
    const float* pb0 = pre + ((size_t)(bid * G + g0) * TENC) * NF + f0;
    const float* pb1 = pre + ((size_t)(bid * G + g1) * TENC) * NF + f1;
    const float* pb2 = pre + ((size_t)(bid * G + g2) * TENC) * NF + f2;

    for (int t = 0; t < TENC; t++) {
        // A: we projection (f32x2 paired over g)
        if (tid < 4 * TENC) {
            int p = tid / TENC, ss = tid % TENC;
            u64 acc = 0ull;
#pragma unroll 8
            for (int k = 0; k < 256; k++) {
                u64 h2 = *(const u64*)(hcT + k * HCT_STR + 2 * p);
                acc = fma2(dup2(wet[k * TENC + ss]), h2, acc);
            }
            float2 v = unpack2(acc);
            we[(2 * p) * TENC + ss] = v.x;
            we[(2 * p + 1) * TENC + ss] = v.y;
        }
        __syncthreads();
        // B: score (s-outer accumulators, coalesced pre reads)
        {
            float a0 = 0.f, a1 = 0.f, a2 = 0.f;
#pragma unroll 4
            for (int ss = 0; ss < TENC; ss++) {
                float vv = vvec[ss];
                if (v0) a0 += tanha(we[g0 * TENC + ss] + pb0[(size_t)ss * NF]) * vv;
                if (v1) a1 += tanha(we[g1 * TENC + ss] + pb1[(size_t)ss * NF]) * vv;
                if (v2) a2 += tanha(we[g2 * TENC + ss] + pb2[(size_t)ss * NF]) * vv;
            }
            float bb = vvec[130];
            if (v0) score[g0 * 132 + f0] = a0 + bb;
            if (v1) score[g1 * 132 + f1] = a1 + bb;
            if (v2) score[g2 * 132 + f2] = a2 + bb;
        }
        __syncthreads();
        if (wid < G) warp_softmax(score + wid * 132, alpha + wid * 132, NF, lane);
        __syncthreads();
        // D: build gate inputs [x_t*alpha | h]
        for (int idx = tid; idx < K * G; idx += NTH) {
            int k = idx >> 3, g = idx & 7;
            int b = bid * G + g;
            float v;
            if (k < NF) {
                float xv = (NF == NF1) ? inp[((size_t)b * TENC + t) * 18 + k + 1]
                                       : g_mid[((size_t)b * TENC + t) * NF2 + k];
                v = xv * alpha[g * 132 + k];
            } else {
                v = hc[g * 256 + (k - NF)];
            }
            inpair[k * G + g] = v;
        }
        __syncthreads();
        // E: gate GEMM
        gates_gemm<K>(Wt, bsum, inpair, gates, tid);
        __syncthreads();
        // F: cell update + output h
        for (int idx = tid; idx < G * HD; idx += NTH) {
            int g = idx >> 7, j = idx & 127;
            float gi = gates[g * NG + j];
            float gf = gates[g * NG + HD + j];
            float gg = gates[g * NG + 2 * HD + j];
            float go = gates[g * NG + 3 * HD + j];
            float c  = hc[g * 256 + HD + j];
            float c2 = sigf(gf) * c + sigf(gi) * tanhacc(gg);
            float h  = sigf(go) * tanhacc(c2);
            hc[g * 256 + j] = h;
            hc[g * 256 + HD + j] = c2;
            hcT[j * HCT_STR + g] = h;
            hcT[(128 + j) * HCT_STR + g] = c2;
            int b = bid * G + g;
            outb[((size_t)b * TENC + t) * ostride + j] = h;
        }
        __syncthreads();
    }
}

// ---------------- decoder smem layout ----------------
#define D_WDT    0
#define D_HC     32768
#define D_HCT    34816
#define D_WD     37376
#define D_SCORE  38400
#define D_ALPHA  38784
#define D_INPAIR 39168
#define D_GATES  41216
#define D_VVEC   45312
#define D_VREG   45448
#define DEC_SMEM_FLOATS 45584

__global__ __launch_bounds__(NTH, 1) void decoder_kernel(
    const float* __restrict__ Vd, const float* __restrict__ Vdb,
    const float* __restrict__ regW, const float* __restrict__ regb,
    float* __restrict__ out) {
    extern __shared__ float sm[];
    float* wdt    = sm + D_WDT;
    float* hc     = sm + D_HC;
    float* hcT    = sm + D_HCT;
    float* wd     = sm + D_WD;
    float* score  = sm + D_SCORE;
    float* alpha  = sm + D_ALPHA;
    float* inpair = sm + D_INPAIR;
    float* gates  = sm + D_GATES;
    float* vvec   = sm + D_VVEC;
    float* vreg   = sm + D_VREG;

    const int tid = threadIdx.x, bid = blockIdx.x;
    const int wid = tid >> 5, lane = tid & 31;

    for (int i = tid; i < 256 * HD; i += NTH) wdt[i] = g_Wdt[i];
    for (int i = tid; i < G * 256; i += NTH) hc[i] = 0.f;
    for (int i = tid; i < 256 * HCT_STR; i += NTH) hcT[i] = 0.f;
    for (int i = tid; i < HD; i += NTH) { vvec[i] = Vd[i]; vreg[i] = regW[i]; }
    if (tid == 0) { vvec[130] = Vdb[0]; vreg[130] = regb[0]; }
    __syncthreads();

    // score item mapping (384 items)
    bool val = tid < G * TENC;
    int sg = val ? tid / TENC : 0, stt = val ? tid % TENC : 0;
    const float* up = g_udT + (size_t)(bid * G + sg) * HD * TENC + stt;

    for (int sd = 0; sd < DSTEPS; sd++) {
        // A: wd projection (paired, all 512 threads)
        {
            int p = tid >> 7, j = tid & 127;
            u64 acc = 0ull;
#pragma unroll 8
            for (int k = 0; k < 256; k++) {
                u64 h2 = *(const u64*)(hcT + k * HCT_STR + 2 * p);
                acc = fma2(dup2(wdt[k * HD + j]), h2, acc);
            }
            float2 v = unpack2(acc);
            wd[(2 * p) * HD + j] = v.x;
            wd[(2 * p + 1) * HD + j] = v.y;
        }
        __syncthreads();
        // B: score (j-outer, coalesced udT reads)
        {
            float a = 0.f;
#pragma unroll 4
            for (int j = 0; j < HD; j++)
                a += tanha(wd[sg * HD + j] + up[(size_t)j * TENC]) * vvec[j];
            if (val) score[sg * TENC + stt] = a + vvec[130];
        }
        __syncthreads();
        if (wid < G) warp_softmax(score + wid * TENC, alpha + wid * TENC, TENC, lane);
        __syncthreads();
        // D: din (t-outer, coalesced fin reads) + inpair
#pragma unroll
        for (int u = 0; u < 2; u++) {
            int idx = tid + u * NTH;
            int g = idx >> 7, j = idx & 127;
            int b = bid * G + g;
            const float* fp = g_fin + ((size_t)b * TENC) * HD + j;
            float a = 0.f;
#pragma unroll 4
            for (int tt = 0; tt < TENC; tt++)
                a += alpha[g * TENC + tt] * fp[(size_t)tt * HD];
            inpair[j * G + g] = a;
            inpair[(HD + j) * G + g] = hc[g * 256 + j];
        }
        __syncthreads();
        gates_gemm<KD>(g_Wtd, g_bd, inpair, gates, tid);
        __syncthreads();
        // F: cell
        for (int idx = tid; idx < G * HD; idx += NTH) {
            int g = idx >> 7, j = idx & 127;
            float gi = gates[g * NG + j];
            float gf = gates[g * NG + HD + j];
            float gg = gates[g * NG + 2 * HD + j];
            float go = gates[g * NG + 3 * HD + j];
            float c  = hc[g * 256 + HD + j];
            float c2 = sigf(gf) * c + sigf(gi) * tanhacc(gg);
            float h  = sigf(go) * tanhacc(c2);
            hc[g * 256 + j] = h;
            hc[g * 256 + HD + j] = c2;
            hcT[j * HCT_STR + g] = h;
            hcT[(128 + j) * HCT_STR + g] = c2;
        }
        __syncthreads();
        // regression output
        if (sd >= DSTEPS - TDEC && wid < G) {
            float a = 0.f;
#pragma unroll
            for (int r = 0; r < 4; r++)
                a += hc[wid * 256 + lane + 32 * r] * vreg[lane + 32 * r];
#pragma unroll
            for (int o = 16; o; o >>= 1) a += __shfl_xor_sync(0xffffffffu, a, o);
            if (lane == 0) {
                int b = bid * G + wid;
                out[(size_t)b * TDEC + (sd - (DSTEPS - TDEC))] = a + vreg[130];
            }
        }
    }
}

// ---------------- launch ----------------
extern "C" void kernel_launch(void* const* d_in, const int* in_sizes, int n_in,
                              void* d_out, int out_size) {
    const float* input_p_q = (const float*)d_in[0];
    const float* label_p   = (const float*)d_in[1];
    const float* Ue1_W = (const float*)d_in[2];
    const float* Ue1_b = (const float*)d_in[3];
    const float* We1_W = (const float*)d_in[4];
    const float* Ve1_W = (const float*)d_in[5];
    const float* Ve1_b = (const float*)d_in[6];
    const float* Ue2_W = (const float*)d_in[7];
    const float* Ue2_b = (const float*)d_in[8];
    const float* We2_W = (const float*)d_in[9];
    const float* Ve2_W = (const float*)d_in[10];
    const float* Ve2_b = (const float*)d_in[11];
    const float* Ud_W  = (const float*)d_in[12];
    const float* Ud_b  = (const float*)d_in[13];
    const float* Wd_W  = (const float*)d_in[14];
    const float* Vd_W  = (const float*)d_in[15];
    const float* Vd_b  = (const float*)d_in[16];
    const float* e1_Wih = (const float*)d_in[17];
    const float* e1_Whh = (const float*)d_in[18];
    const float* e1_bih = (const float*)d_in[19];
    const float* e1_bhh = (const float*)d_in[20];
    const float* e2_Wih = (const float*)d_in[21];
    const float* e2_Whh = (const float*)d_in[22];
    const float* e2_bih = (const float*)d_in[23];
    const float* e2_bhh = (const float*)d_in[24];
    const float* d_Wih  = (const float*)d_in[25];
    const float* d_Whh  = (const float*)d_in[26];
    const float* d_bih  = (const float*)d_in[27];
    const float* d_bhh  = (const float*)d_in[28];
    const float* reg_W  = (const float*)d_in[29];
    const float* reg_b  = (const float*)d_in[30];
    float* out = (float*)d_out;

    float *p_Wt1, *p_Wt2, *p_Wet1, *p_Wet2;
    float *p_b1, *p_b2, *p_pre1, *p_pre2, *p_mid, *p_fin;
    cudaGetSymbolAddress((void**)&p_Wt1, g_Wt1);
    cudaGetSymbolAddress((void**)&p_Wt2, g_Wt2);
    cudaGetSymbolAddress((void**)&p_Wet1, g_Wet1);
    cudaGetSymbolAddress((void**)&p_Wet2, g_Wet2);
    cudaGetSymbolAddress((void**)&p_b1, g_b1);
    cudaGetSymbolAddress((void**)&p_b2, g_b2);
    cudaGetSymbolAddress((void**)&p_pre1, g_pre1);
    cudaGetSymbolAddress((void**)&p_pre2, g_pre2);
    cudaGetSymbolAddress((void**)&p_mid, g_mid);
    cudaGetSymbolAddress((void**)&p_fin, g_fin);

    const int STAGE_SMEM = STAGE_SMEM_FLOATS * 4;
    const int DEC_SMEM   = DEC_SMEM_FLOATS * 4;
    const int UD_SMEM    = (16384 + TENC * 129) * 4;

    cudaFuncSetAttribute(stage_kernel<K1, NF1>,
                         cudaFuncAttributeMaxDynamicSharedMemorySize, STAGE_SMEM);
    cudaFuncSetAttribute(stage_kernel<K2, NF2>,
                         cudaFuncAttributeMaxDynamicSharedMemorySize, STAGE_SMEM);
    cudaFuncSetAttribute(decoder_kernel,
                         cudaFuncAttributeMaxDynamicSharedMemorySize, DEC_SMEM);
    cudaFuncSetAttribute(ud_kernel,
                         cudaFuncAttributeMaxDynamicSharedMemorySize, UD_SMEM);

    setup_kernel<<<128, 256>>>(e1_Wih, e1_Whh, e2_Wih, e2_Whh, d_Wih, d_Whh,
                               We1_W, We2_W, Wd_W, Ud_W,
                               e1_bih, e1_bhh, e2_bih, e2_bhh, d_bih, d_bhh);
    pre1_kernel<<<BTOT, 256>>>(input_p_q, label_p, Ue1_W, Ue1_b);
    stage_kernel<K1, NF1><<<NCTA, NTH, STAGE_SMEM>>>(
        input_p_q, Ve1_W, Ve1_b, p_Wt1, p_b1, p_Wet1, p_pre1, p_mid, NF2);
    pre2_kernel<<<BTOT, 256>>>(Ue2_W, Ue2_b);
    stage_kernel<K2, NF2><<<NCTA, NTH, STAGE_SMEM>>>(
        input_p_q, Ve2_W, Ve2_b, p_Wt2, p_b2, p_Wet2, p_pre2, p_fin, HD);
    ud_kernel<<<BTOT, 256, UD_SMEM>>>(Ud_b);
    decoder_kernel<<<NCTA, NTH, DEC_SMEM>>>(Vd_W, Vd_b, reg_W, reg_b, out);
}